// round 13
// baseline (speedup 1.0000x reference)
#include <cuda_runtime.h>
#include <cstdint>
#include <cstddef>

#define Bb 4
#define Ss 2048
#define Ee 1024
#define Hh 16
#define Dd 64
#define BS (Bb*Ss)

// ---------------- static device scratch ----------------
__device__ float g_q[BS*Ee];       // tf32 bits, pre-scaled by invt/8
__device__ float g_k[BS*Ee];       // tf32 bits
__device__ float g_v[BS*Ee];       // tf32 bits
__device__ float g_attn[BS*Ee];
__device__ float g_biasmat[(size_t)Bb*Ss*Ss];   // 64 MB, pre-multiplied by invt_q
__device__ float g_invtemp[BS];
__device__ float g_keybias[BS];
__device__ int   g_maskint[BS];
__device__ int   g_maskisbyte;

// ---------------- helpers ----------------
__device__ __forceinline__ uint32_t f2tf(float f) {
    uint32_t u;
    asm("cvt.rna.tf32.f32 %0, %1;" : "=r"(u) : "f"(f));
    return u;
}
__device__ __forceinline__ void mma_tf32(float* c, uint32_t a0, uint32_t a1,
                                         uint32_t a2, uint32_t a3,
                                         uint32_t b0, uint32_t b1) {
    asm volatile("mma.sync.aligned.m16n8k8.row.col.f32.tf32.tf32.f32 "
                 "{%0,%1,%2,%3}, {%4,%5,%6,%7}, {%8,%9}, {%0,%1,%2,%3};"
                 : "+f"(c[0]), "+f"(c[1]), "+f"(c[2]), "+f"(c[3])
                 : "r"(a0), "r"(a1), "r"(a2), "r"(a3), "r"(b0), "r"(b1));
}
__device__ __forceinline__ void cp16(float* dst, const float* src) {
    uint32_t d = (uint32_t)__cvta_generic_to_shared(dst);
    asm volatile("cp.async.cg.shared.global [%0], [%1], 16;" :: "r"(d), "l"(src));
}

// ---------------- mask dtype detection ----------------
__global__ void detect_mask_kernel(const unsigned char* __restrict__ m) {
    __shared__ int cnt;
    if (threadIdx.x == 0) cnt = 0;
    __syncthreads();
    int local = 0;
    for (int i = threadIdx.x; i < 8192; i += blockDim.x) local += (m[i] != 0);
    atomicAdd(&cnt, local);
    __syncthreads();
    if (threadIdx.x == 0) g_maskisbyte = (cnt > 2500) ? 1 : 0;
}

// ---------------- per-token prep ----------------
__global__ void prep_kernel(const void* __restrict__ maskraw,
                            const float* __restrict__ explore,
                            const float* __restrict__ exploit,
                            const float* __restrict__ mu,
                            const float* __restrict__ sigma) {
    int i = blockIdx.x * blockDim.x + threadIdx.x;
    if (i >= BS) return;
    int mk;
    if (g_maskisbyte) mk = (((const unsigned char*)maskraw)[i] != 0);
    else              mk = (((const int*)maskraw)[i] != 0);
    g_maskint[i] = mk;
    float t = 1.0f + 0.5f * explore[i] - 0.5f * exploit[i];
    t = fminf(fmaxf(t, 0.5f), 2.0f);
    if (mk) t = 1.0f;
    g_invtemp[i] = 1.0f / t;
    const float* mr = mu + (size_t)i * 64;
    const float* sr = sigma + (size_t)i * 64;
    float sq = 0.f, sm = 0.f;
#pragma unroll
    for (int j = 0; j < 64; j++) { sq += mr[j] * mr[j]; sm += sr[j]; }
    g_keybias[i] = -0.5f * (sq * (1.0f / 64.0f)) - 0.5f * (sm * (1.0f / 64.0f));
}

// ---------------- bias matrix (exact fp32), pre-multiplied by invt_q ----------------
__global__ __launch_bounds__(256) void bias_kernel(const float* __restrict__ assign,
                                                   const float* __restrict__ mu) {
    __shared__ float Qa[32][33], Ka[64][33], Qm[32][65], Km[64][65];
    const int b = blockIdx.z, q0 = blockIdx.y * 32, k0 = blockIdx.x * 64;
    const int tid = threadIdx.x, ty = tid >> 4, tx = tid & 15;

    {
        int r = tid >> 3, c4 = tid & 7;
        float4 v = *(const float4*)(assign + (size_t)(b*Ss + q0 + r) * 32 + c4 * 4);
        Qa[r][c4*4+0] = v.x*0.5f; Qa[r][c4*4+1] = v.y*0.5f;
        Qa[r][c4*4+2] = v.z*0.5f; Qa[r][c4*4+3] = v.w*0.5f;
    }
#pragma unroll
    for (int p = 0; p < 2; p++) {
        int fi = tid + 256*p, r = fi >> 3, c4 = fi & 7;
        float4 v = *(const float4*)(assign + (size_t)(b*Ss + k0 + r) * 32 + c4 * 4);
        Ka[r][c4*4+0] = v.x; Ka[r][c4*4+1] = v.y; Ka[r][c4*4+2] = v.z; Ka[r][c4*4+3] = v.w;
    }
    {
        const float s = 1.0f / 64.0f;
#pragma unroll
        for (int p = 0; p < 2; p++) {
            int fi = tid + 256*p, r = fi >> 4, c4 = fi & 15;
            float4 v = *(const float4*)(mu + (size_t)(b*Ss + q0 + r) * 64 + c4 * 4);
            Qm[r][c4*4+0] = v.x*s; Qm[r][c4*4+1] = v.y*s; Qm[r][c4*4+2] = v.z*s; Qm[r][c4*4+3] = v.w*s;
        }
    }
#pragma unroll
    for (int p = 0; p < 4; p++) {
        int fi = tid + 256*p, r = fi >> 4, c4 = fi & 15;
        float4 v = *(const float4*)(mu + (size_t)(b*Ss + k0 + r) * 64 + c4 * 4);
        Km[r][c4*4+0] = v.x; Km[r][c4*4+1] = v.y; Km[r][c4*4+2] = v.z; Km[r][c4*4+3] = v.w;
    }
    __syncthreads();

    float acc[2][4] = {{0.f,0.f,0.f,0.f},{0.f,0.f,0.f,0.f}};
#pragma unroll 4
    for (int c = 0; c < 32; c++) {
        float q0a = Qa[ty*2][c], q1a = Qa[ty*2+1][c];
#pragma unroll
        for (int i = 0; i < 4; i++) {
            float ka = Ka[tx*4+i][c];
            acc[0][i] += q0a * ka; acc[1][i] += q1a * ka;
        }
    }
#pragma unroll 4
    for (int c = 0; c < 64; c++) {
        float q0m = Qm[ty*2][c], q1m = Qm[ty*2+1][c];
#pragma unroll
        for (int i = 0; i < 4; i++) {
            float km = Km[tx*4+i][c];
            acc[0][i] += q0m * km; acc[1][i] += q1m * km;
        }
    }
    float4 kb = *(const float4*)(g_keybias + b*Ss + k0 + tx*4);
#pragma unroll
    for (int jj = 0; jj < 2; jj++) {
        float it = g_invtemp[b*Ss + q0 + ty*2 + jj];
        float4 o;
        o.x = (acc[jj][0] + kb.x) * it; o.y = (acc[jj][1] + kb.y) * it;
        o.z = (acc[jj][2] + kb.z) * it; o.w = (acc[jj][3] + kb.w) * it;
        *(float4*)(g_biasmat + ((size_t)(b*Ss + q0 + ty*2 + jj)) * Ss + k0 + tx*4) = o;
    }
}

// ---------------- TF32 GEMM with cp.async double buffering ----------------
// C = A[M,1024] @ W[N,1024]^T + bias. 128x128 tile, KC=16 x 2 stages, 8 warps.
// MODE 1: fp32 out, zero masked rows. MODE 2: tf32-bits out. MODE 3: tf32 bits of (x*invt[m]/8).
template<int MODE>
__global__ __launch_bounds__(256) void sgemm_tc(const float* __restrict__ A,
                                                const float* __restrict__ W,
                                                const float* __restrict__ bias,
                                                float* __restrict__ C) {
    __shared__ float As[2][128 * 20];
    __shared__ float Bs[2][128 * 20];
    const int m0 = blockIdx.y * 128, n0 = blockIdx.x * 128;
    const int tid = threadIdx.x;
    const int wid = tid >> 5, lane = tid & 31;
    const int wm = wid >> 2, wn = wid & 3;
    const int g = lane >> 2, tig = lane & 3;
    const int lr = tid >> 2, lc = tid & 3;

    const float* a0p = A + (size_t)(m0 + lr)      * 1024 + lc*4;
    const float* a1p = A + (size_t)(m0 + 64 + lr) * 1024 + lc*4;
    const float* b0p = W + (size_t)(n0 + lr)      * 1024 + lc*4;
    const float* b1p = W + (size_t)(n0 + 64 + lr) * 1024 + lc*4;

    float cacc[4][4][4];
#pragma unroll
    for (int mt = 0; mt < 4; mt++)
#pragma unroll
        for (int nt = 0; nt < 4; nt++)
#pragma unroll
            for (int i = 0; i < 4; i++) cacc[mt][nt][i] = 0.f;

    // prologue: stage 0
    cp16(&As[0][lr*20 + lc*4], a0p);
    cp16(&As[0][(lr+64)*20 + lc*4], a1p);
    cp16(&Bs[0][lr*20 + lc*4], b0p);
    cp16(&Bs[0][(lr+64)*20 + lc*4], b1p);
    asm volatile("cp.async.commit_group;");

    for (int kt = 0; kt < 64; kt++) {
        const int cur = kt & 1;
        if (kt < 63) {
            const int nk = (kt + 1) * 16;
            cp16(&As[cur^1][lr*20 + lc*4], a0p + nk);
            cp16(&As[cur^1][(lr+64)*20 + lc*4], a1p + nk);
            cp16(&Bs[cur^1][lr*20 + lc*4], b0p + nk);
            cp16(&Bs[cur^1][(lr+64)*20 + lc*4], b1p + nk);
            asm volatile("cp.async.commit_group;");
            asm volatile("cp.async.wait_group 1;");
        } else {
            asm volatile("cp.async.wait_group 0;");
        }
        __syncthreads();

        const float* Ac = As[cur];
        const float* Bc = Bs[cur];
#pragma unroll
        for (int ks = 0; ks < 2; ks++) {
            const int kk = ks*8 + tig;
            uint32_t af[4][4];
#pragma unroll
            for (int mt = 0; mt < 4; mt++) {
                int m = wm*64 + mt*16 + g;
                af[mt][0] = f2tf(Ac[m * 20 + kk]);
                af[mt][1] = f2tf(Ac[(m + 8) * 20 + kk]);
                af[mt][2] = f2tf(Ac[m * 20 + kk + 4]);
                af[mt][3] = f2tf(Ac[(m + 8) * 20 + kk + 4]);
            }
#pragma unroll
            for (int nt = 0; nt < 4; nt++) {
                int n = wn*32 + nt*8 + g;
                uint32_t fb0 = f2tf(Bc[n * 20 + kk]);
                uint32_t fb1 = f2tf(Bc[n * 20 + kk + 4]);
#pragma unroll
                for (int mt = 0; mt < 4; mt++)
                    mma_tf32(cacc[mt][nt], af[mt][0], af[mt][1], af[mt][2], af[mt][3], fb0, fb1);
            }
        }
        __syncthreads();
    }

#pragma unroll
    for (int mt = 0; mt < 4; mt++) {
        int m = m0 + wm*64 + mt*16 + g;
        bool z0 = (MODE == 1) && (g_maskint[m] != 0);
        bool z1 = (MODE == 1) && (g_maskint[m + 8] != 0);
        float s0 = 1.f, s1 = 1.f;
        if (MODE == 3) {
            s0 = g_invtemp[m] * 0.125f;
            s1 = g_invtemp[m + 8] * 0.125f;
        }
#pragma unroll
        for (int nt = 0; nt < 4; nt++) {
            int n = n0 + wn*32 + nt*8 + tig*2;
            float bx = bias[n], by = bias[n + 1];
            float v00 = cacc[mt][nt][0] + bx, v01 = cacc[mt][nt][1] + by;
            float v10 = cacc[mt][nt][2] + bx, v11 = cacc[mt][nt][3] + by;
            float2 o0, o1;
            if (MODE == 2) {
                o0.x = __uint_as_float(f2tf(v00)); o0.y = __uint_as_float(f2tf(v01));
                o1.x = __uint_as_float(f2tf(v10)); o1.y = __uint_as_float(f2tf(v11));
            } else if (MODE == 3) {
                o0.x = __uint_as_float(f2tf(v00 * s0)); o0.y = __uint_as_float(f2tf(v01 * s0));
                o1.x = __uint_as_float(f2tf(v10 * s1)); o1.y = __uint_as_float(f2tf(v11 * s1));
            } else {
                o0.x = z0 ? 0.f : v00; o0.y = z0 ? 0.f : v01;
                o1.x = z1 ? 0.f : v10; o1.y = z1 ? 0.f : v11;
            }
            *(float2*)(C + (size_t)m * 1024 + n)       = o0;
            *(float2*)(C + (size_t)(m + 8) * 1024 + n) = o1;
        }
    }
}

// ---------------- TF32 flash attention: 128q x 128k tiles, 8 q-warps ----------------
#define QS_OFF 0
#define KS_OFF 8704
#define VS_OFF 17408
#define BP_OFF 26112
#define ATT_SMEM (43008 * 4)
__global__ __launch_bounds__(256, 1) void attn_tc() {
    extern __shared__ uint32_t smu[];
    uint32_t* Qs  = smu + QS_OFF;
    uint32_t* Ks  = smu + KS_OFF;
    uint32_t* Vs  = smu + VS_OFF;
    uint32_t* BPu = smu + BP_OFF;
    float*    BPf = (float*)BPu;
    __shared__ int mk[128];

    // grid: x = head (16 heads of same q-tile adjacent -> bias tile L2 reuse)
    const int b = blockIdx.z, h = blockIdx.x, q0 = blockIdx.y * 128;
    const int tid = threadIdx.x;
    const int wid = tid >> 5, lane = tid & 31;
    const int g = lane >> 2, tig = lane & 3;
    const int qb = wid * 16;
    const int bS = b * Ss;

    // Q: pre-scaled tf32 bits -> direct copy
#pragma unroll
    for (int p = 0; p < 8; p++) {
        int fi = tid + 256*p, r = fi >> 4, c4 = fi & 15;
        uint4 u = *(const uint4*)(g_q + (size_t)(bS + q0 + r) * 1024 + h*64 + c4*4);
        *(uint4*)&Qs[r * 68 + c4*4] = u;
    }
    const int r0 = qb + g, r1 = qb + g + 8;
    float m0_ = -1e30f, m1_ = -1e30f, l0_ = 0.f, l1_ = 0.f;
    float oacc[8][4];
#pragma unroll
    for (int nt = 0; nt < 8; nt++)
#pragma unroll
        for (int i = 0; i < 4; i++) oacc[nt][i] = 0.f;

    for (int kt0 = 0; kt0 < Ss; kt0 += 128) {
        __syncthreads();
#pragma unroll
        for (int p = 0; p < 8; p++) {
            int fi = tid + 256*p, r = fi >> 4, c4 = fi & 15;
            uint4 uk = *(const uint4*)(g_k + (size_t)(bS + kt0 + r) * 1024 + h*64 + c4*4);
            *(uint4*)&Ks[r * 68 + c4*4] = uk;
            uint4 uv = *(const uint4*)(g_v + (size_t)(bS + kt0 + r) * 1024 + h*64 + c4*4);
            *(uint4*)&Vs[r * 68 + c4*4] = uv;
        }
#pragma unroll
        for (int p = 0; p < 16; p++) {
            int fi = tid + 256*p, r = fi >> 5, c4 = fi & 31;
            float4 bv = *(const float4*)(g_biasmat + ((size_t)(bS + q0 + r)) * Ss + kt0 + c4*4);
            *(float4*)&BPf[r * 132 + c4*4] = bv;
        }
        if (tid < 128) mk[tid] = g_maskint[bS + kt0 + tid];
        __syncthreads();

        // S = Q' K^T
        float sacc[16][4];
#pragma unroll
        for (int nt = 0; nt < 16; nt++)
#pragma unroll
            for (int i = 0; i < 4; i++) sacc[nt][i] = 0.f;
#pragma unroll
        for (int ds = 0; ds < 8; ds++) {
            const int kk = ds*8 + tig;
            uint32_t a0 = Qs[r0 * 68 + kk], a1 = Qs[r1 * 68 + kk];
            uint32_t a2 = Qs[r0 * 68 + kk + 4], a3 = Qs[r1 * 68 + kk + 4];
#pragma unroll
            for (int nt = 0; nt < 16; nt++) {
                uint32_t fb0 = Ks[(nt*8 + g) * 68 + kk];
                uint32_t fb1 = Ks[(nt*8 + g) * 68 + kk + 4];
                mma_tf32(sacc[nt], a0, a1, a2, a3, fb0, fb1);
            }
        }

        // softmax (rows r0, r1 live entirely in this quad)
        uint32_t mbits = 0;
        float bm0 = -1e30f, bm1 = -1e30f;
#pragma unroll
        for (int nt = 0; nt < 16; nt++) {
            int col = nt*8 + tig*2;
            float2 bz0 = *(float2*)&BPf[r0 * 132 + col];
            float2 bz1 = *(float2*)&BPf[r1 * 132 + col];
            int k0m = mk[col], k1m = mk[col + 1];
            mbits |= (uint32_t)(k0m ? 1 : 0) << (2*nt);
            mbits |= (uint32_t)(k1m ? 1 : 0) << (2*nt + 1);
            float s00 = k0m ? -1e30f : sacc[nt][0] + bz0.x;
            float s01 = k1m ? -1e30f : sacc[nt][1] + bz0.y;
            float s10 = k0m ? -1e30f : sacc[nt][2] + bz1.x;
            float s11 = k1m ? -1e30f : sacc[nt][3] + bz1.y;
            sacc[nt][0] = s00; sacc[nt][1] = s01; sacc[nt][2] = s10; sacc[nt][3] = s11;
            bm0 = fmaxf(bm0, fmaxf(s00, s01));
            bm1 = fmaxf(bm1, fmaxf(s10, s11));
        }
        bm0 = fmaxf(bm0, __shfl_xor_sync(0xffffffffu, bm0, 1));
        bm0 = fmaxf(bm0, __shfl_xor_sync(0xffffffffu, bm0, 2));
        bm1 = fmaxf(bm1, __shfl_xor_sync(0xffffffffu, bm1, 1));
        bm1 = fmaxf(bm1, __shfl_xor_sync(0xffffffffu, bm1, 2));
        float mn0 = fmaxf(m0_, bm0), mn1 = fmaxf(m1_, bm1);
        float sc0 = __expf(m0_ - mn0), sc1 = __expf(m1_ - mn1);
        m0_ = mn0; m1_ = mn1;
        float rs0 = 0.f, rs1 = 0.f;
#pragma unroll
        for (int nt = 0; nt < 16; nt++) {
            int col = nt*8 + tig*2;
            float p00 = ((mbits >> (2*nt))   & 1u) ? 0.f : __expf(sacc[nt][0] - mn0);
            float p01 = ((mbits >> (2*nt+1)) & 1u) ? 0.f : __expf(sacc[nt][1] - mn0);
            float p10 = ((mbits >> (2*nt))   & 1u) ? 0.f : __expf(sacc[nt][2] - mn1);
            float p11 = ((mbits >> (2*nt+1)) & 1u) ? 0.f : __expf(sacc[nt][3] - mn1);
            rs0 += p00 + p01; rs1 += p10 + p11;
            uint2 u0 = {f2tf(p00), f2tf(p01)};
            uint2 u1 = {f2tf(p10), f2tf(p11)};
            *(uint2*)&BPu[r0 * 132 + col] = u0;
            *(uint2*)&BPu[r1 * 132 + col] = u1;
        }
        rs0 += __shfl_xor_sync(0xffffffffu, rs0, 1);
        rs0 += __shfl_xor_sync(0xffffffffu, rs0, 2);
        rs1 += __shfl_xor_sync(0xffffffffu, rs1, 1);
        rs1 += __shfl_xor_sync(0xffffffffu, rs1, 2);
        l0_ = l0_ * sc0 + rs0;
        l1_ = l1_ * sc1 + rs1;
#pragma unroll
        for (int nt = 0; nt < 8; nt++) {
            oacc[nt][0] *= sc0; oacc[nt][1] *= sc0;
            oacc[nt][2] *= sc1; oacc[nt][3] *= sc1;
        }
        __syncwarp();

        // O += P V
#pragma unroll
        for (int ks = 0; ks < 16; ks++) {
            const int kr = ks*8 + tig;
            uint32_t a0 = BPu[r0 * 132 + kr], a1 = BPu[r1 * 132 + kr];
            uint32_t a2 = BPu[r0 * 132 + kr + 4], a3 = BPu[r1 * 132 + kr + 4];
#pragma unroll
            for (int nt = 0; nt < 8; nt++) {
                uint32_t fb0 = Vs[kr * 68 + nt*8 + g];
                uint32_t fb1 = Vs[(kr + 4) * 68 + nt*8 + g];
                mma_tf32(oacc[nt], a0, a1, a2, a3, fb0, fb1);
            }
        }
    }

    float inv0 = 1.0f / fmaxf(l0_, 1e-8f);
    float inv1 = 1.0f / fmaxf(l1_, 1e-8f);
#pragma unroll
    for (int nt = 0; nt < 8; nt++) {
        int d = nt*8 + tig*2;
        float2 o0 = {oacc[nt][0] * inv0, oacc[nt][1] * inv0};
        float2 o1 = {oacc[nt][2] * inv1, oacc[nt][3] * inv1};
        *(float2*)(g_attn + (size_t)(bS + q0 + r0) * 1024 + h*64 + d) = o0;
        *(float2*)(g_attn + (size_t)(bS + q0 + r1) * 1024 + h*64 + d) = o1;
    }
}

// ---------------- launch ----------------
extern "C" void kernel_launch(void* const* d_in, const int* in_sizes, int n_in,
                              void* d_out, int out_size) {
    const float* his     = (const float*)d_in[0];
    const void*  mask    = d_in[1];
    const float* mu      = (const float*)d_in[2];
    const float* sigma   = (const float*)d_in[3];
    const float* assign  = (const float*)d_in[4];
    const float* explore = (const float*)d_in[5];
    const float* exploit = (const float*)d_in[6];
    const float* Wq = (const float*)d_in[7];  const float* bq = (const float*)d_in[8];
    const float* Wk = (const float*)d_in[9];  const float* bk = (const float*)d_in[10];
    const float* Wv = (const float*)d_in[11]; const float* bv = (const float*)d_in[12];
    const float* Wo = (const float*)d_in[13]; const float* bo = (const float*)d_in[14];
    float* out = (float*)d_out;

    float *gq, *gk, *gv, *ga;
    cudaGetSymbolAddress((void**)&gq, g_q);
    cudaGetSymbolAddress((void**)&gk, g_k);
    cudaGetSymbolAddress((void**)&gv, g_v);
    cudaGetSymbolAddress((void**)&ga, g_attn);

    static int attr_set = 0;
    if (!attr_set) {
        cudaFuncSetAttribute(attn_tc, cudaFuncAttributeMaxDynamicSharedMemorySize, ATT_SMEM);
        attr_set = 1;
    }

    detect_mask_kernel<<<1, 256>>>((const unsigned char*)mask);
    prep_kernel<<<BS/256, 256>>>(mask, explore, exploit, mu, sigma);
    bias_kernel<<<dim3(Ss/64, Ss/32, Bb), 256>>>(assign, mu);
    sgemm_tc<3><<<dim3(8, 64), 256>>>(his, Wq, bq, gq);   // Q: tf32, pre-scaled invt/8
    sgemm_tc<2><<<dim3(8, 64), 256>>>(his, Wk, bk, gk);   // K: tf32
    sgemm_tc<2><<<dim3(8, 64), 256>>>(his, Wv, bv, gv);   // V: tf32
    attn_tc<<<dim3(Hh, Ss/128, Bb), 256, ATT_SMEM>>>();
    sgemm_tc<1><<<dim3(8, 64), 256>>>(ga, Wo, bo, out);   // O: fp32 + mask-zero
}

// round 14
// speedup vs baseline: 1.0013x; 1.0013x over previous
#include <cuda_runtime.h>
#include <cstdint>
#include <cstddef>

#define Bb 4
#define Ss 2048
#define Ee 1024
#define Hh 16
#define Dd 64
#define BS (Bb*Ss)

// ---------------- static device scratch ----------------
__device__ float g_q[BS*Ee];       // tf32 bits, pre-scaled by invt/8
__device__ float g_k[BS*Ee];       // tf32 bits
__device__ float g_v[BS*Ee];       // tf32 bits
__device__ float g_attn[BS*Ee];
__device__ float g_biasmat[(size_t)Bb*Ss*Ss];   // 64 MB, pre-multiplied by invt_q
__device__ float g_invtemp[BS];
__device__ float g_keybias[BS];
__device__ int   g_maskint[BS];
__device__ int   g_maskisbyte;

// ---------------- helpers ----------------
__device__ __forceinline__ uint32_t f2tf(float f) {
    uint32_t u;
    asm("cvt.rna.tf32.f32 %0, %1;" : "=r"(u) : "f"(f));
    return u;
}
__device__ __forceinline__ void mma_tf32(float* c, uint32_t a0, uint32_t a1,
                                         uint32_t a2, uint32_t a3,
                                         uint32_t b0, uint32_t b1) {
    asm volatile("mma.sync.aligned.m16n8k8.row.col.f32.tf32.tf32.f32 "
                 "{%0,%1,%2,%3}, {%4,%5,%6,%7}, {%8,%9}, {%0,%1,%2,%3};"
                 : "+f"(c[0]), "+f"(c[1]), "+f"(c[2]), "+f"(c[3])
                 : "r"(a0), "r"(a1), "r"(a2), "r"(a3), "r"(b0), "r"(b1));
}
__device__ __forceinline__ void cp16(float* dst, const float* src) {
    uint32_t d = (uint32_t)__cvta_generic_to_shared(dst);
    asm volatile("cp.async.cg.shared.global [%0], [%1], 16;" :: "r"(d), "l"(src));
}

// ---------------- mask dtype detection ----------------
__global__ void detect_mask_kernel(const unsigned char* __restrict__ m) {
    __shared__ int cnt;
    if (threadIdx.x == 0) cnt = 0;
    __syncthreads();
    int local = 0;
    for (int i = threadIdx.x; i < 8192; i += blockDim.x) local += (m[i] != 0);
    atomicAdd(&cnt, local);
    __syncthreads();
    if (threadIdx.x == 0) g_maskisbyte = (cnt > 2500) ? 1 : 0;
}

// ---------------- per-token prep ----------------
__global__ void prep_kernel(const void* __restrict__ maskraw,
                            const float* __restrict__ explore,
                            const float* __restrict__ exploit,
                            const float* __restrict__ mu,
                            const float* __restrict__ sigma) {
    int i = blockIdx.x * blockDim.x + threadIdx.x;
    if (i >= BS) return;
    int mk;
    if (g_maskisbyte) mk = (((const unsigned char*)maskraw)[i] != 0);
    else              mk = (((const int*)maskraw)[i] != 0);
    g_maskint[i] = mk;
    float t = 1.0f + 0.5f * explore[i] - 0.5f * exploit[i];
    t = fminf(fmaxf(t, 0.5f), 2.0f);
    if (mk) t = 1.0f;
    g_invtemp[i] = 1.0f / t;
    const float* mr = mu + (size_t)i * 64;
    const float* sr = sigma + (size_t)i * 64;
    float sq = 0.f, sm = 0.f;
#pragma unroll
    for (int j = 0; j < 64; j++) { sq += mr[j] * mr[j]; sm += sr[j]; }
    g_keybias[i] = -0.5f * (sq * (1.0f / 64.0f)) - 0.5f * (sm * (1.0f / 64.0f));
}

// ---------------- bias matrix (exact fp32), pre-multiplied by invt_q ----------------
__global__ __launch_bounds__(256) void bias_kernel(const float* __restrict__ assign,
                                                   const float* __restrict__ mu) {
    __shared__ float Qa[32][33], Ka[64][33], Qm[32][65], Km[64][65];
    const int b = blockIdx.z, q0 = blockIdx.y * 32, k0 = blockIdx.x * 64;
    const int tid = threadIdx.x, ty = tid >> 4, tx = tid & 15;

    {
        int r = tid >> 3, c4 = tid & 7;
        float4 v = *(const float4*)(assign + (size_t)(b*Ss + q0 + r) * 32 + c4 * 4);
        Qa[r][c4*4+0] = v.x*0.5f; Qa[r][c4*4+1] = v.y*0.5f;
        Qa[r][c4*4+2] = v.z*0.5f; Qa[r][c4*4+3] = v.w*0.5f;
    }
#pragma unroll
    for (int p = 0; p < 2; p++) {
        int fi = tid + 256*p, r = fi >> 3, c4 = fi & 7;
        float4 v = *(const float4*)(assign + (size_t)(b*Ss + k0 + r) * 32 + c4 * 4);
        Ka[r][c4*4+0] = v.x; Ka[r][c4*4+1] = v.y; Ka[r][c4*4+2] = v.z; Ka[r][c4*4+3] = v.w;
    }
    {
        const float s = 1.0f / 64.0f;
#pragma unroll
        for (int p = 0; p < 2; p++) {
            int fi = tid + 256*p, r = fi >> 4, c4 = fi & 15;
            float4 v = *(const float4*)(mu + (size_t)(b*Ss + q0 + r) * 64 + c4 * 4);
            Qm[r][c4*4+0] = v.x*s; Qm[r][c4*4+1] = v.y*s; Qm[r][c4*4+2] = v.z*s; Qm[r][c4*4+3] = v.w*s;
        }
    }
#pragma unroll
    for (int p = 0; p < 4; p++) {
        int fi = tid + 256*p, r = fi >> 4, c4 = fi & 15;
        float4 v = *(const float4*)(mu + (size_t)(b*Ss + k0 + r) * 64 + c4 * 4);
        Km[r][c4*4+0] = v.x; Km[r][c4*4+1] = v.y; Km[r][c4*4+2] = v.z; Km[r][c4*4+3] = v.w;
    }
    __syncthreads();

    float acc[2][4] = {{0.f,0.f,0.f,0.f},{0.f,0.f,0.f,0.f}};
#pragma unroll 4
    for (int c = 0; c < 32; c++) {
        float q0a = Qa[ty*2][c], q1a = Qa[ty*2+1][c];
#pragma unroll
        for (int i = 0; i < 4; i++) {
            float ka = Ka[tx*4+i][c];
            acc[0][i] += q0a * ka; acc[1][i] += q1a * ka;
        }
    }
#pragma unroll 4
    for (int c = 0; c < 64; c++) {
        float q0m = Qm[ty*2][c], q1m = Qm[ty*2+1][c];
#pragma unroll
        for (int i = 0; i < 4; i++) {
            float km = Km[tx*4+i][c];
            acc[0][i] += q0m * km; acc[1][i] += q1m * km;
        }
    }
    float4 kb = *(const float4*)(g_keybias + b*Ss + k0 + tx*4);
#pragma unroll
    for (int jj = 0; jj < 2; jj++) {
        float it = g_invtemp[b*Ss + q0 + ty*2 + jj];
        float4 o;
        o.x = (acc[jj][0] + kb.x) * it; o.y = (acc[jj][1] + kb.y) * it;
        o.z = (acc[jj][2] + kb.z) * it; o.w = (acc[jj][3] + kb.w) * it;
        *(float4*)(g_biasmat + ((size_t)(b*Ss + q0 + ty*2 + jj)) * Ss + k0 + tx*4) = o;
    }
}

// ---------------- TF32 GEMM with cp.async double buffering ----------------
// C = A[M,1024] @ W[N,1024]^T + bias. 128x128 tile, KC=16 x 2 stages, 8 warps.
// MODE 1: fp32 out, zero masked rows. MODE 2: tf32-bits out. MODE 3: tf32 bits of (x*invt[m]/8).
template<int MODE>
__global__ __launch_bounds__(256) void sgemm_tc(const float* __restrict__ A,
                                                const float* __restrict__ W,
                                                const float* __restrict__ bias,
                                                float* __restrict__ C) {
    __shared__ float As[2][128 * 20];
    __shared__ float Bs[2][128 * 20];
    const int m0 = blockIdx.y * 128, n0 = blockIdx.x * 128;
    const int tid = threadIdx.x;
    const int wid = tid >> 5, lane = tid & 31;
    const int wm = wid >> 2, wn = wid & 3;
    const int g = lane >> 2, tig = lane & 3;
    const int lr = tid >> 2, lc = tid & 3;

    const float* a0p = A + (size_t)(m0 + lr)      * 1024 + lc*4;
    const float* a1p = A + (size_t)(m0 + 64 + lr) * 1024 + lc*4;
    const float* b0p = W + (size_t)(n0 + lr)      * 1024 + lc*4;
    const float* b1p = W + (size_t)(n0 + 64 + lr) * 1024 + lc*4;

    float cacc[4][4][4];
#pragma unroll
    for (int mt = 0; mt < 4; mt++)
#pragma unroll
        for (int nt = 0; nt < 4; nt++)
#pragma unroll
            for (int i = 0; i < 4; i++) cacc[mt][nt][i] = 0.f;

    // prologue: stage 0
    cp16(&As[0][lr*20 + lc*4], a0p);
    cp16(&As[0][(lr+64)*20 + lc*4], a1p);
    cp16(&Bs[0][lr*20 + lc*4], b0p);
    cp16(&Bs[0][(lr+64)*20 + lc*4], b1p);
    asm volatile("cp.async.commit_group;");

    for (int kt = 0; kt < 64; kt++) {
        const int cur = kt & 1;
        if (kt < 63) {
            const int nk = (kt + 1) * 16;
            cp16(&As[cur^1][lr*20 + lc*4], a0p + nk);
            cp16(&As[cur^1][(lr+64)*20 + lc*4], a1p + nk);
            cp16(&Bs[cur^1][lr*20 + lc*4], b0p + nk);
            cp16(&Bs[cur^1][(lr+64)*20 + lc*4], b1p + nk);
            asm volatile("cp.async.commit_group;");
            asm volatile("cp.async.wait_group 1;");
        } else {
            asm volatile("cp.async.wait_group 0;");
        }
        __syncthreads();

        const float* Ac = As[cur];
        const float* Bc = Bs[cur];
#pragma unroll
        for (int ks = 0; ks < 2; ks++) {
            const int kk = ks*8 + tig;
            uint32_t af[4][4];
#pragma unroll
            for (int mt = 0; mt < 4; mt++) {
                int m = wm*64 + mt*16 + g;
                af[mt][0] = f2tf(Ac[m * 20 + kk]);
                af[mt][1] = f2tf(Ac[(m + 8) * 20 + kk]);
                af[mt][2] = f2tf(Ac[m * 20 + kk + 4]);
                af[mt][3] = f2tf(Ac[(m + 8) * 20 + kk + 4]);
            }
#pragma unroll
            for (int nt = 0; nt < 4; nt++) {
                int n = wn*32 + nt*8 + g;
                uint32_t fb0 = f2tf(Bc[n * 20 + kk]);
                uint32_t fb1 = f2tf(Bc[n * 20 + kk + 4]);
#pragma unroll
                for (int mt = 0; mt < 4; mt++)
                    mma_tf32(cacc[mt][nt], af[mt][0], af[mt][1], af[mt][2], af[mt][3], fb0, fb1);
            }
        }
        __syncthreads();
    }

#pragma unroll
    for (int mt = 0; mt < 4; mt++) {
        int m = m0 + wm*64 + mt*16 + g;
        bool z0 = (MODE == 1) && (g_maskint[m] != 0);
        bool z1 = (MODE == 1) && (g_maskint[m + 8] != 0);
        float s0 = 1.f, s1 = 1.f;
        if (MODE == 3) {
            s0 = g_invtemp[m] * 0.125f;
            s1 = g_invtemp[m + 8] * 0.125f;
        }
#pragma unroll
        for (int nt = 0; nt < 4; nt++) {
            int n = n0 + wn*32 + nt*8 + tig*2;
            float bx = bias[n], by = bias[n + 1];
            float v00 = cacc[mt][nt][0] + bx, v01 = cacc[mt][nt][1] + by;
            float v10 = cacc[mt][nt][2] + bx, v11 = cacc[mt][nt][3] + by;
            float2 o0, o1;
            if (MODE == 2) {
                o0.x = __uint_as_float(f2tf(v00)); o0.y = __uint_as_float(f2tf(v01));
                o1.x = __uint_as_float(f2tf(v10)); o1.y = __uint_as_float(f2tf(v11));
            } else if (MODE == 3) {
                o0.x = __uint_as_float(f2tf(v00 * s0)); o0.y = __uint_as_float(f2tf(v01 * s0));
                o1.x = __uint_as_float(f2tf(v10 * s1)); o1.y = __uint_as_float(f2tf(v11 * s1));
            } else {
                o0.x = z0 ? 0.f : v00; o0.y = z0 ? 0.f : v01;
                o1.x = z1 ? 0.f : v10; o1.y = z1 ? 0.f : v11;
            }
            *(float2*)(C + (size_t)m * 1024 + n)       = o0;
            *(float2*)(C + (size_t)(m + 8) * 1024 + n) = o1;
        }
    }
}

// ---------------- TF32 flash attention: 128q x 128k tiles, 8 q-warps ----------------
#define QS_OFF 0
#define KS_OFF 8704
#define VS_OFF 17408
#define BP_OFF 26112
#define ATT_SMEM (43008 * 4)
__global__ __launch_bounds__(256, 1) void attn_tc() {
    extern __shared__ uint32_t smu[];
    uint32_t* Qs  = smu + QS_OFF;
    uint32_t* Ks  = smu + KS_OFF;
    uint32_t* Vs  = smu + VS_OFF;
    uint32_t* BPu = smu + BP_OFF;
    float*    BPf = (float*)BPu;
    __shared__ int mk[128];

    // grid: x = head (16 heads of same q-tile adjacent -> bias tile L2 reuse)
    const int b = blockIdx.z, h = blockIdx.x, q0 = blockIdx.y * 128;
    const int tid = threadIdx.x;
    const int wid = tid >> 5, lane = tid & 31;
    const int g = lane >> 2, tig = lane & 3;
    const int qb = wid * 16;
    const int bS = b * Ss;

    // Q: pre-scaled tf32 bits -> direct copy
#pragma unroll
    for (int p = 0; p < 8; p++) {
        int fi = tid + 256*p, r = fi >> 4, c4 = fi & 15;
        uint4 u = *(const uint4*)(g_q + (size_t)(bS + q0 + r) * 1024 + h*64 + c4*4);
        *(uint4*)&Qs[r * 68 + c4*4] = u;
    }
    const int r0 = qb + g, r1 = qb + g + 8;
    float m0_ = -1e30f, m1_ = -1e30f, l0_ = 0.f, l1_ = 0.f;
    float oacc[8][4];
#pragma unroll
    for (int nt = 0; nt < 8; nt++)
#pragma unroll
        for (int i = 0; i < 4; i++) oacc[nt][i] = 0.f;

    for (int kt0 = 0; kt0 < Ss; kt0 += 128) {
        __syncthreads();
#pragma unroll
        for (int p = 0; p < 8; p++) {
            int fi = tid + 256*p, r = fi >> 4, c4 = fi & 15;
            uint4 uk = *(const uint4*)(g_k + (size_t)(bS + kt0 + r) * 1024 + h*64 + c4*4);
            *(uint4*)&Ks[r * 68 + c4*4] = uk;
            uint4 uv = *(const uint4*)(g_v + (size_t)(bS + kt0 + r) * 1024 + h*64 + c4*4);
            *(uint4*)&Vs[r * 68 + c4*4] = uv;
        }
#pragma unroll
        for (int p = 0; p < 16; p++) {
            int fi = tid + 256*p, r = fi >> 5, c4 = fi & 31;
            float4 bv = *(const float4*)(g_biasmat + ((size_t)(bS + q0 + r)) * Ss + kt0 + c4*4);
            *(float4*)&BPf[r * 132 + c4*4] = bv;
        }
        if (tid < 128) mk[tid] = g_maskint[bS + kt0 + tid];
        __syncthreads();

        // S = Q' K^T
        float sacc[16][4];
#pragma unroll
        for (int nt = 0; nt < 16; nt++)
#pragma unroll
            for (int i = 0; i < 4; i++) sacc[nt][i] = 0.f;
#pragma unroll
        for (int ds = 0; ds < 8; ds++) {
            const int kk = ds*8 + tig;
            uint32_t a0 = Qs[r0 * 68 + kk], a1 = Qs[r1 * 68 + kk];
            uint32_t a2 = Qs[r0 * 68 + kk + 4], a3 = Qs[r1 * 68 + kk + 4];
#pragma unroll
            for (int nt = 0; nt < 16; nt++) {
                uint32_t fb0 = Ks[(nt*8 + g) * 68 + kk];
                uint32_t fb1 = Ks[(nt*8 + g) * 68 + kk + 4];
                mma_tf32(sacc[nt], a0, a1, a2, a3, fb0, fb1);
            }
        }

        // softmax (rows r0, r1 live entirely in this quad)
        uint32_t mbits = 0;
        float bm0 = -1e30f, bm1 = -1e30f;
#pragma unroll
        for (int nt = 0; nt < 16; nt++) {
            int col = nt*8 + tig*2;
            float2 bz0 = *(float2*)&BPf[r0 * 132 + col];
            float2 bz1 = *(float2*)&BPf[r1 * 132 + col];
            int k0m = mk[col], k1m = mk[col + 1];
            mbits |= (uint32_t)(k0m ? 1 : 0) << (2*nt);
            mbits |= (uint32_t)(k1m ? 1 : 0) << (2*nt + 1);
            float s00 = k0m ? -1e30f : sacc[nt][0] + bz0.x;
            float s01 = k1m ? -1e30f : sacc[nt][1] + bz0.y;
            float s10 = k0m ? -1e30f : sacc[nt][2] + bz1.x;
            float s11 = k1m ? -1e30f : sacc[nt][3] + bz1.y;
            sacc[nt][0] = s00; sacc[nt][1] = s01; sacc[nt][2] = s10; sacc[nt][3] = s11;
            bm0 = fmaxf(bm0, fmaxf(s00, s01));
            bm1 = fmaxf(bm1, fmaxf(s10, s11));
        }
        bm0 = fmaxf(bm0, __shfl_xor_sync(0xffffffffu, bm0, 1));
        bm0 = fmaxf(bm0, __shfl_xor_sync(0xffffffffu, bm0, 2));
        bm1 = fmaxf(bm1, __shfl_xor_sync(0xffffffffu, bm1, 1));
        bm1 = fmaxf(bm1, __shfl_xor_sync(0xffffffffu, bm1, 2));
        float mn0 = fmaxf(m0_, bm0), mn1 = fmaxf(m1_, bm1);
        float sc0 = __expf(m0_ - mn0), sc1 = __expf(m1_ - mn1);
        m0_ = mn0; m1_ = mn1;
        float rs0 = 0.f, rs1 = 0.f;
#pragma unroll
        for (int nt = 0; nt < 16; nt++) {
            int col = nt*8 + tig*2;
            float p00 = ((mbits >> (2*nt))   & 1u) ? 0.f : __expf(sacc[nt][0] - mn0);
            float p01 = ((mbits >> (2*nt+1)) & 1u) ? 0.f : __expf(sacc[nt][1] - mn0);
            float p10 = ((mbits >> (2*nt))   & 1u) ? 0.f : __expf(sacc[nt][2] - mn1);
            float p11 = ((mbits >> (2*nt+1)) & 1u) ? 0.f : __expf(sacc[nt][3] - mn1);
            rs0 += p00 + p01; rs1 += p10 + p11;
            uint2 u0 = {f2tf(p00), f2tf(p01)};
            uint2 u1 = {f2tf(p10), f2tf(p11)};
            *(uint2*)&BPu[r0 * 132 + col] = u0;
            *(uint2*)&BPu[r1 * 132 + col] = u1;
        }
        rs0 += __shfl_xor_sync(0xffffffffu, rs0, 1);
        rs0 += __shfl_xor_sync(0xffffffffu, rs0, 2);
        rs1 += __shfl_xor_sync(0xffffffffu, rs1, 1);
        rs1 += __shfl_xor_sync(0xffffffffu, rs1, 2);
        l0_ = l0_ * sc0 + rs0;
        l1_ = l1_ * sc1 + rs1;
#pragma unroll
        for (int nt = 0; nt < 8; nt++) {
            oacc[nt][0] *= sc0; oacc[nt][1] *= sc0;
            oacc[nt][2] *= sc1; oacc[nt][3] *= sc1;
        }
        __syncwarp();

        // O += P V
#pragma unroll
        for (int ks = 0; ks < 16; ks++) {
            const int kr = ks*8 + tig;
            uint32_t a0 = BPu[r0 * 132 + kr], a1 = BPu[r1 * 132 + kr];
            uint32_t a2 = BPu[r0 * 132 + kr + 4], a3 = BPu[r1 * 132 + kr + 4];
#pragma unroll
            for (int nt = 0; nt < 8; nt++) {
                uint32_t fb0 = Vs[kr * 68 + nt*8 + g];
                uint32_t fb1 = Vs[(kr + 4) * 68 + nt*8 + g];
                mma_tf32(oacc[nt], a0, a1, a2, a3, fb0, fb1);
            }
        }
    }

    float inv0 = 1.0f / fmaxf(l0_, 1e-8f);
    float inv1 = 1.0f / fmaxf(l1_, 1e-8f);
#pragma unroll
    for (int nt = 0; nt < 8; nt++) {
        int d = nt*8 + tig*2;
        float2 o0 = {oacc[nt][0] * inv0, oacc[nt][1] * inv0};
        float2 o1 = {oacc[nt][2] * inv1, oacc[nt][3] * inv1};
        *(float2*)(g_attn + (size_t)(bS + q0 + r0) * 1024 + h*64 + d) = o0;
        *(float2*)(g_attn + (size_t)(bS + q0 + r1) * 1024 + h*64 + d) = o1;
    }
}

// ---------------- launch ----------------
extern "C" void kernel_launch(void* const* d_in, const int* in_sizes, int n_in,
                              void* d_out, int out_size) {
    const float* his     = (const float*)d_in[0];
    const void*  mask    = d_in[1];
    const float* mu      = (const float*)d_in[2];
    const float* sigma   = (const float*)d_in[3];
    const float* assign  = (const float*)d_in[4];
    const float* explore = (const float*)d_in[5];
    const float* exploit = (const float*)d_in[6];
    const float* Wq = (const float*)d_in[7];  const float* bq = (const float*)d_in[8];
    const float* Wk = (const float*)d_in[9];  const float* bk = (const float*)d_in[10];
    const float* Wv = (const float*)d_in[11]; const float* bv = (const float*)d_in[12];
    const float* Wo = (const float*)d_in[13]; const float* bo = (const float*)d_in[14];
    float* out = (float*)d_out;

    float *gq, *gk, *gv, *ga;
    cudaGetSymbolAddress((void**)&gq, g_q);
    cudaGetSymbolAddress((void**)&gk, g_k);
    cudaGetSymbolAddress((void**)&gv, g_v);
    cudaGetSymbolAddress((void**)&ga, g_attn);

    static int attr_set = 0;
    if (!attr_set) {
        cudaFuncSetAttribute(attn_tc, cudaFuncAttributeMaxDynamicSharedMemorySize, ATT_SMEM);
        attr_set = 1;
    }

    detect_mask_kernel<<<1, 256>>>((const unsigned char*)mask);
    prep_kernel<<<BS/256, 256>>>(mask, explore, exploit, mu, sigma);
    bias_kernel<<<dim3(Ss/64, Ss/32, Bb), 256>>>(assign, mu);
    sgemm_tc<3><<<dim3(8, 64), 256>>>(his, Wq, bq, gq);   // Q: tf32, pre-scaled invt/8
    sgemm_tc<2><<<dim3(8, 64), 256>>>(his, Wk, bk, gk);   // K: tf32
    sgemm_tc<2><<<dim3(8, 64), 256>>>(his, Wv, bv, gv);   // V: tf32
    attn_tc<<<dim3(Hh, Ss/128, Bb), 256, ATT_SMEM>>>();
    sgemm_tc<1><<<dim3(8, 64), 256>>>(ga, Wo, bo, out);   // O: fp32 + mask-zero
}

// round 15
// speedup vs baseline: 1.0021x; 1.0009x over previous
#include <cuda_runtime.h>
#include <cstdint>
#include <cstddef>

#define Bb 4
#define Ss 2048
#define Ee 1024
#define Hh 16
#define Dd 64
#define BS (Bb*Ss)

// ---------------- static device scratch ----------------
__device__ float g_q[BS*Ee];       // tf32 bits, pre-scaled by invt/8
__device__ float g_k[BS*Ee];       // tf32 bits
__device__ float g_v[BS*Ee];       // tf32 bits
__device__ float g_attn[BS*Ee];
__device__ float g_biasmat[(size_t)Bb*Ss*Ss];   // 64 MB, pre-multiplied by invt_q
__device__ float g_invtemp[BS];
__device__ float g_keybias[BS];
__device__ int   g_maskint[BS];
__device__ int   g_maskisbyte;

// ---------------- helpers ----------------
__device__ __forceinline__ uint32_t f2tf(float f) {
    uint32_t u;
    asm("cvt.rna.tf32.f32 %0, %1;" : "=r"(u) : "f"(f));
    return u;
}
__device__ __forceinline__ void mma_tf32(float* c, uint32_t a0, uint32_t a1,
                                         uint32_t a2, uint32_t a3,
                                         uint32_t b0, uint32_t b1) {
    asm volatile("mma.sync.aligned.m16n8k8.row.col.f32.tf32.tf32.f32 "
                 "{%0,%1,%2,%3}, {%4,%5,%6,%7}, {%8,%9}, {%0,%1,%2,%3};"
                 : "+f"(c[0]), "+f"(c[1]), "+f"(c[2]), "+f"(c[3])
                 : "r"(a0), "r"(a1), "r"(a2), "r"(a3), "r"(b0), "r"(b1));
}
__device__ __forceinline__ void cp16(float* dst, const float* src) {
    uint32_t d = (uint32_t)__cvta_generic_to_shared(dst);
    asm volatile("cp.async.cg.shared.global [%0], [%1], 16;" :: "r"(d), "l"(src));
}

// ---------------- mask dtype detection ----------------
__global__ void detect_mask_kernel(const unsigned char* __restrict__ m) {
    __shared__ int cnt;
    if (threadIdx.x == 0) cnt = 0;
    __syncthreads();
    int local = 0;
    for (int i = threadIdx.x; i < 8192; i += blockDim.x) local += (m[i] != 0);
    atomicAdd(&cnt, local);
    __syncthreads();
    if (threadIdx.x == 0) g_maskisbyte = (cnt > 2500) ? 1 : 0;
}

// ---------------- per-token prep ----------------
__global__ void prep_kernel(const void* __restrict__ maskraw,
                            const float* __restrict__ explore,
                            const float* __restrict__ exploit,
                            const float* __restrict__ mu,
                            const float* __restrict__ sigma) {
    int i = blockIdx.x * blockDim.x + threadIdx.x;
    if (i >= BS) return;
    int mk;
    if (g_maskisbyte) mk = (((const unsigned char*)maskraw)[i] != 0);
    else              mk = (((const int*)maskraw)[i] != 0);
    g_maskint[i] = mk;
    float t = 1.0f + 0.5f * explore[i] - 0.5f * exploit[i];
    t = fminf(fmaxf(t, 0.5f), 2.0f);
    if (mk) t = 1.0f;
    g_invtemp[i] = 1.0f / t;
    const float* mr = mu + (size_t)i * 64;
    const float* sr = sigma + (size_t)i * 64;
    float sq = 0.f, sm = 0.f;
#pragma unroll
    for (int j = 0; j < 64; j++) { sq += mr[j] * mr[j]; sm += sr[j]; }
    g_keybias[i] = -0.5f * (sq * (1.0f / 64.0f)) - 0.5f * (sm * (1.0f / 64.0f));
}

// ---------------- bias matrix (exact fp32), pre-multiplied by invt_q ----------------
__global__ __launch_bounds__(256) void bias_kernel(const float* __restrict__ assign,
                                                   const float* __restrict__ mu) {
    __shared__ float Qa[32][33], Ka[64][33], Qm[32][65], Km[64][65];
    const int b = blockIdx.z, q0 = blockIdx.y * 32, k0 = blockIdx.x * 64;
    const int tid = threadIdx.x, ty = tid >> 4, tx = tid & 15;

    {
        int r = tid >> 3, c4 = tid & 7;
        float4 v = *(const float4*)(assign + (size_t)(b*Ss + q0 + r) * 32 + c4 * 4);
        Qa[r][c4*4+0] = v.x*0.5f; Qa[r][c4*4+1] = v.y*0.5f;
        Qa[r][c4*4+2] = v.z*0.5f; Qa[r][c4*4+3] = v.w*0.5f;
    }
#pragma unroll
    for (int p = 0; p < 2; p++) {
        int fi = tid + 256*p, r = fi >> 3, c4 = fi & 7;
        float4 v = *(const float4*)(assign + (size_t)(b*Ss + k0 + r) * 32 + c4 * 4);
        Ka[r][c4*4+0] = v.x; Ka[r][c4*4+1] = v.y; Ka[r][c4*4+2] = v.z; Ka[r][c4*4+3] = v.w;
    }
    {
        const float s = 1.0f / 64.0f;
#pragma unroll
        for (int p = 0; p < 2; p++) {
            int fi = tid + 256*p, r = fi >> 4, c4 = fi & 15;
            float4 v = *(const float4*)(mu + (size_t)(b*Ss + q0 + r) * 64 + c4 * 4);
            Qm[r][c4*4+0] = v.x*s; Qm[r][c4*4+1] = v.y*s; Qm[r][c4*4+2] = v.z*s; Qm[r][c4*4+3] = v.w*s;
        }
    }
#pragma unroll
    for (int p = 0; p < 4; p++) {
        int fi = tid + 256*p, r = fi >> 4, c4 = fi & 15;
        float4 v = *(const float4*)(mu + (size_t)(b*Ss + k0 + r) * 64 + c4 * 4);
        Km[r][c4*4+0] = v.x; Km[r][c4*4+1] = v.y; Km[r][c4*4+2] = v.z; Km[r][c4*4+3] = v.w;
    }
    __syncthreads();

    float acc[2][4] = {{0.f,0.f,0.f,0.f},{0.f,0.f,0.f,0.f}};
#pragma unroll 4
    for (int c = 0; c < 32; c++) {
        float q0a = Qa[ty*2][c], q1a = Qa[ty*2+1][c];
#pragma unroll
        for (int i = 0; i < 4; i++) {
            float ka = Ka[tx*4+i][c];
            acc[0][i] += q0a * ka; acc[1][i] += q1a * ka;
        }
    }
#pragma unroll 4
    for (int c = 0; c < 64; c++) {
        float q0m = Qm[ty*2][c], q1m = Qm[ty*2+1][c];
#pragma unroll
        for (int i = 0; i < 4; i++) {
            float km = Km[tx*4+i][c];
            acc[0][i] += q0m * km; acc[1][i] += q1m * km;
        }
    }
    float4 kb = *(const float4*)(g_keybias + b*Ss + k0 + tx*4);
#pragma unroll
    for (int jj = 0; jj < 2; jj++) {
        float it = g_invtemp[b*Ss + q0 + ty*2 + jj];
        float4 o;
        o.x = (acc[jj][0] + kb.x) * it; o.y = (acc[jj][1] + kb.y) * it;
        o.z = (acc[jj][2] + kb.z) * it; o.w = (acc[jj][3] + kb.w) * it;
        *(float4*)(g_biasmat + ((size_t)(b*Ss + q0 + ty*2 + jj)) * Ss + k0 + tx*4) = o;
    }
}

// ---------------- TF32 GEMM with cp.async double buffering ----------------
// C = A[M,1024] @ W[N,1024]^T + bias. 128x128 tile, KC=16 x 2 stages, 8 warps.
// MODE 1: fp32 out, zero masked rows. MODE 2: tf32-bits out. MODE 3: tf32 bits of (x*invt[m]/8).
template<int MODE>
__global__ __launch_bounds__(256) void sgemm_tc(const float* __restrict__ A,
                                                const float* __restrict__ W,
                                                const float* __restrict__ bias,
                                                float* __restrict__ C) {
    __shared__ float As[2][128 * 20];
    __shared__ float Bs[2][128 * 20];
    const int m0 = blockIdx.y * 128, n0 = blockIdx.x * 128;
    const int tid = threadIdx.x;
    const int wid = tid >> 5, lane = tid & 31;
    const int wm = wid >> 2, wn = wid & 3;
    const int g = lane >> 2, tig = lane & 3;
    const int lr = tid >> 2, lc = tid & 3;

    const float* a0p = A + (size_t)(m0 + lr)      * 1024 + lc*4;
    const float* a1p = A + (size_t)(m0 + 64 + lr) * 1024 + lc*4;
    const float* b0p = W + (size_t)(n0 + lr)      * 1024 + lc*4;
    const float* b1p = W + (size_t)(n0 + 64 + lr) * 1024 + lc*4;

    float cacc[4][4][4];
#pragma unroll
    for (int mt = 0; mt < 4; mt++)
#pragma unroll
        for (int nt = 0; nt < 4; nt++)
#pragma unroll
            for (int i = 0; i < 4; i++) cacc[mt][nt][i] = 0.f;

    // prologue: stage 0
    cp16(&As[0][lr*20 + lc*4], a0p);
    cp16(&As[0][(lr+64)*20 + lc*4], a1p);
    cp16(&Bs[0][lr*20 + lc*4], b0p);
    cp16(&Bs[0][(lr+64)*20 + lc*4], b1p);
    asm volatile("cp.async.commit_group;");

    for (int kt = 0; kt < 64; kt++) {
        const int cur = kt & 1;
        if (kt < 63) {
            const int nk = (kt + 1) * 16;
            cp16(&As[cur^1][lr*20 + lc*4], a0p + nk);
            cp16(&As[cur^1][(lr+64)*20 + lc*4], a1p + nk);
            cp16(&Bs[cur^1][lr*20 + lc*4], b0p + nk);
            cp16(&Bs[cur^1][(lr+64)*20 + lc*4], b1p + nk);
            asm volatile("cp.async.commit_group;");
            asm volatile("cp.async.wait_group 1;");
        } else {
            asm volatile("cp.async.wait_group 0;");
        }
        __syncthreads();

        const float* Ac = As[cur];
        const float* Bc = Bs[cur];
#pragma unroll
        for (int ks = 0; ks < 2; ks++) {
            const int kk = ks*8 + tig;
            uint32_t af[4][4];
#pragma unroll
            for (int mt = 0; mt < 4; mt++) {
                int m = wm*64 + mt*16 + g;
                af[mt][0] = f2tf(Ac[m * 20 + kk]);
                af[mt][1] = f2tf(Ac[(m + 8) * 20 + kk]);
                af[mt][2] = f2tf(Ac[m * 20 + kk + 4]);
                af[mt][3] = f2tf(Ac[(m + 8) * 20 + kk + 4]);
            }
#pragma unroll
            for (int nt = 0; nt < 4; nt++) {
                int n = wn*32 + nt*8 + g;
                uint32_t fb0 = f2tf(Bc[n * 20 + kk]);
                uint32_t fb1 = f2tf(Bc[n * 20 + kk + 4]);
#pragma unroll
                for (int mt = 0; mt < 4; mt++)
                    mma_tf32(cacc[mt][nt], af[mt][0], af[mt][1], af[mt][2], af[mt][3], fb0, fb1);
            }
        }
        __syncthreads();
    }

#pragma unroll
    for (int mt = 0; mt < 4; mt++) {
        int m = m0 + wm*64 + mt*16 + g;
        bool z0 = (MODE == 1) && (g_maskint[m] != 0);
        bool z1 = (MODE == 1) && (g_maskint[m + 8] != 0);
        float s0 = 1.f, s1 = 1.f;
        if (MODE == 3) {
            s0 = g_invtemp[m] * 0.125f;
            s1 = g_invtemp[m + 8] * 0.125f;
        }
#pragma unroll
        for (int nt = 0; nt < 4; nt++) {
            int n = n0 + wn*32 + nt*8 + tig*2;
            float bx = bias[n], by = bias[n + 1];
            float v00 = cacc[mt][nt][0] + bx, v01 = cacc[mt][nt][1] + by;
            float v10 = cacc[mt][nt][2] + bx, v11 = cacc[mt][nt][3] + by;
            float2 o0, o1;
            if (MODE == 2) {
                o0.x = __uint_as_float(f2tf(v00)); o0.y = __uint_as_float(f2tf(v01));
                o1.x = __uint_as_float(f2tf(v10)); o1.y = __uint_as_float(f2tf(v11));
            } else if (MODE == 3) {
                o0.x = __uint_as_float(f2tf(v00 * s0)); o0.y = __uint_as_float(f2tf(v01 * s0));
                o1.x = __uint_as_float(f2tf(v10 * s1)); o1.y = __uint_as_float(f2tf(v11 * s1));
            } else {
                o0.x = z0 ? 0.f : v00; o0.y = z0 ? 0.f : v01;
                o1.x = z1 ? 0.f : v10; o1.y = z1 ? 0.f : v11;
            }
            *(float2*)(C + (size_t)m * 1024 + n)       = o0;
            *(float2*)(C + (size_t)(m + 8) * 1024 + n) = o1;
        }
    }
}

// ---------------- TF32 flash attention: 128q x 128k tiles, 8 q-warps ----------------
#define QS_OFF 0
#define KS_OFF 8704
#define VS_OFF 17408
#define BP_OFF 26112
#define ATT_SMEM (43008 * 4)
__global__ __launch_bounds__(256, 1) void attn_tc() {
    extern __shared__ uint32_t smu[];
    uint32_t* Qs  = smu + QS_OFF;
    uint32_t* Ks  = smu + KS_OFF;
    uint32_t* Vs  = smu + VS_OFF;
    uint32_t* BPu = smu + BP_OFF;
    float*    BPf = (float*)BPu;
    __shared__ int mk[128];

    // grid: x = head (16 heads of same q-tile adjacent -> bias tile L2 reuse)
    const int b = blockIdx.z, h = blockIdx.x, q0 = blockIdx.y * 128;
    const int tid = threadIdx.x;
    const int wid = tid >> 5, lane = tid & 31;
    const int g = lane >> 2, tig = lane & 3;
    const int qb = wid * 16;
    const int bS = b * Ss;

    // Q: pre-scaled tf32 bits -> direct copy
#pragma unroll
    for (int p = 0; p < 8; p++) {
        int fi = tid + 256*p, r = fi >> 4, c4 = fi & 15;
        uint4 u = *(const uint4*)(g_q + (size_t)(bS + q0 + r) * 1024 + h*64 + c4*4);
        *(uint4*)&Qs[r * 68 + c4*4] = u;
    }
    const int r0 = qb + g, r1 = qb + g + 8;
    float m0_ = -1e30f, m1_ = -1e30f, l0_ = 0.f, l1_ = 0.f;
    float oacc[8][4];
#pragma unroll
    for (int nt = 0; nt < 8; nt++)
#pragma unroll
        for (int i = 0; i < 4; i++) oacc[nt][i] = 0.f;

    for (int kt0 = 0; kt0 < Ss; kt0 += 128) {
        __syncthreads();
#pragma unroll
        for (int p = 0; p < 8; p++) {
            int fi = tid + 256*p, r = fi >> 4, c4 = fi & 15;
            uint4 uk = *(const uint4*)(g_k + (size_t)(bS + kt0 + r) * 1024 + h*64 + c4*4);
            *(uint4*)&Ks[r * 68 + c4*4] = uk;
            uint4 uv = *(const uint4*)(g_v + (size_t)(bS + kt0 + r) * 1024 + h*64 + c4*4);
            *(uint4*)&Vs[r * 68 + c4*4] = uv;
        }
#pragma unroll
        for (int p = 0; p < 16; p++) {
            int fi = tid + 256*p, r = fi >> 5, c4 = fi & 31;
            float4 bv = *(const float4*)(g_biasmat + ((size_t)(bS + q0 + r)) * Ss + kt0 + c4*4);
            *(float4*)&BPf[r * 132 + c4*4] = bv;
        }
        if (tid < 128) mk[tid] = g_maskint[bS + kt0 + tid];
        __syncthreads();

        // S = Q' K^T
        float sacc[16][4];
#pragma unroll
        for (int nt = 0; nt < 16; nt++)
#pragma unroll
            for (int i = 0; i < 4; i++) sacc[nt][i] = 0.f;
#pragma unroll
        for (int ds = 0; ds < 8; ds++) {
            const int kk = ds*8 + tig;
            uint32_t a0 = Qs[r0 * 68 + kk], a1 = Qs[r1 * 68 + kk];
            uint32_t a2 = Qs[r0 * 68 + kk + 4], a3 = Qs[r1 * 68 + kk + 4];
#pragma unroll
            for (int nt = 0; nt < 16; nt++) {
                uint32_t fb0 = Ks[(nt*8 + g) * 68 + kk];
                uint32_t fb1 = Ks[(nt*8 + g) * 68 + kk + 4];
                mma_tf32(sacc[nt], a0, a1, a2, a3, fb0, fb1);
            }
        }

        // softmax (rows r0, r1 live entirely in this quad)
        uint32_t mbits = 0;
        float bm0 = -1e30f, bm1 = -1e30f;
#pragma unroll
        for (int nt = 0; nt < 16; nt++) {
            int col = nt*8 + tig*2;
            float2 bz0 = *(float2*)&BPf[r0 * 132 + col];
            float2 bz1 = *(float2*)&BPf[r1 * 132 + col];
            int k0m = mk[col], k1m = mk[col + 1];
            mbits |= (uint32_t)(k0m ? 1 : 0) << (2*nt);
            mbits |= (uint32_t)(k1m ? 1 : 0) << (2*nt + 1);
            float s00 = k0m ? -1e30f : sacc[nt][0] + bz0.x;
            float s01 = k1m ? -1e30f : sacc[nt][1] + bz0.y;
            float s10 = k0m ? -1e30f : sacc[nt][2] + bz1.x;
            float s11 = k1m ? -1e30f : sacc[nt][3] + bz1.y;
            sacc[nt][0] = s00; sacc[nt][1] = s01; sacc[nt][2] = s10; sacc[nt][3] = s11;
            bm0 = fmaxf(bm0, fmaxf(s00, s01));
            bm1 = fmaxf(bm1, fmaxf(s10, s11));
        }
        bm0 = fmaxf(bm0, __shfl_xor_sync(0xffffffffu, bm0, 1));
        bm0 = fmaxf(bm0, __shfl_xor_sync(0xffffffffu, bm0, 2));
        bm1 = fmaxf(bm1, __shfl_xor_sync(0xffffffffu, bm1, 1));
        bm1 = fmaxf(bm1, __shfl_xor_sync(0xffffffffu, bm1, 2));
        float mn0 = fmaxf(m0_, bm0), mn1 = fmaxf(m1_, bm1);
        float sc0 = __expf(m0_ - mn0), sc1 = __expf(m1_ - mn1);
        m0_ = mn0; m1_ = mn1;
        float rs0 = 0.f, rs1 = 0.f;
#pragma unroll
        for (int nt = 0; nt < 16; nt++) {
            int col = nt*8 + tig*2;
            float p00 = ((mbits >> (2*nt))   & 1u) ? 0.f : __expf(sacc[nt][0] - mn0);
            float p01 = ((mbits >> (2*nt+1)) & 1u) ? 0.f : __expf(sacc[nt][1] - mn0);
            float p10 = ((mbits >> (2*nt))   & 1u) ? 0.f : __expf(sacc[nt][2] - mn1);
            float p11 = ((mbits >> (2*nt+1)) & 1u) ? 0.f : __expf(sacc[nt][3] - mn1);
            rs0 += p00 + p01; rs1 += p10 + p11;
            uint2 u0 = {f2tf(p00), f2tf(p01)};
            uint2 u1 = {f2tf(p10), f2tf(p11)};
            *(uint2*)&BPu[r0 * 132 + col] = u0;
            *(uint2*)&BPu[r1 * 132 + col] = u1;
        }
        rs0 += __shfl_xor_sync(0xffffffffu, rs0, 1);
        rs0 += __shfl_xor_sync(0xffffffffu, rs0, 2);
        rs1 += __shfl_xor_sync(0xffffffffu, rs1, 1);
        rs1 += __shfl_xor_sync(0xffffffffu, rs1, 2);
        l0_ = l0_ * sc0 + rs0;
        l1_ = l1_ * sc1 + rs1;
#pragma unroll
        for (int nt = 0; nt < 8; nt++) {
            oacc[nt][0] *= sc0; oacc[nt][1] *= sc0;
            oacc[nt][2] *= sc1; oacc[nt][3] *= sc1;
        }
        __syncwarp();

        // O += P V
#pragma unroll
        for (int ks = 0; ks < 16; ks++) {
            const int kr = ks*8 + tig;
            uint32_t a0 = BPu[r0 * 132 + kr], a1 = BPu[r1 * 132 + kr];
            uint32_t a2 = BPu[r0 * 132 + kr + 4], a3 = BPu[r1 * 132 + kr + 4];
#pragma unroll
            for (int nt = 0; nt < 8; nt++) {
                uint32_t fb0 = Vs[kr * 68 + nt*8 + g];
                uint32_t fb1 = Vs[(kr + 4) * 68 + nt*8 + g];
                mma_tf32(oacc[nt], a0, a1, a2, a3, fb0, fb1);
            }
        }
    }

    float inv0 = 1.0f / fmaxf(l0_, 1e-8f);
    float inv1 = 1.0f / fmaxf(l1_, 1e-8f);
#pragma unroll
    for (int nt = 0; nt < 8; nt++) {
        int d = nt*8 + tig*2;
        float2 o0 = {oacc[nt][0] * inv0, oacc[nt][1] * inv0};
        float2 o1 = {oacc[nt][2] * inv1, oacc[nt][3] * inv1};
        *(float2*)(g_attn + (size_t)(bS + q0 + r0) * 1024 + h*64 + d) = o0;
        *(float2*)(g_attn + (size_t)(bS + q0 + r1) * 1024 + h*64 + d) = o1;
    }
}

// ---------------- launch ----------------
extern "C" void kernel_launch(void* const* d_in, const int* in_sizes, int n_in,
                              void* d_out, int out_size) {
    const float* his     = (const float*)d_in[0];
    const void*  mask    = d_in[1];
    const float* mu      = (const float*)d_in[2];
    const float* sigma   = (const float*)d_in[3];
    const float* assign  = (const float*)d_in[4];
    const float* explore = (const float*)d_in[5];
    const float* exploit = (const float*)d_in[6];
    const float* Wq = (const float*)d_in[7];  const float* bq = (const float*)d_in[8];
    const float* Wk = (const float*)d_in[9];  const float* bk = (const float*)d_in[10];
    const float* Wv = (const float*)d_in[11]; const float* bv = (const float*)d_in[12];
    const float* Wo = (const float*)d_in[13]; const float* bo = (const float*)d_in[14];
    float* out = (float*)d_out;

    float *gq, *gk, *gv, *ga;
    cudaGetSymbolAddress((void**)&gq, g_q);
    cudaGetSymbolAddress((void**)&gk, g_k);
    cudaGetSymbolAddress((void**)&gv, g_v);
    cudaGetSymbolAddress((void**)&ga, g_attn);

    static int attr_set = 0;
    if (!attr_set) {
        cudaFuncSetAttribute(attn_tc, cudaFuncAttributeMaxDynamicSharedMemorySize, ATT_SMEM);
        attr_set = 1;
    }

    detect_mask_kernel<<<1, 256>>>((const unsigned char*)mask);
    prep_kernel<<<BS/256, 256>>>(mask, explore, exploit, mu, sigma);
    bias_kernel<<<dim3(Ss/64, Ss/32, Bb), 256>>>(assign, mu);
    sgemm_tc<3><<<dim3(8, 64), 256>>>(his, Wq, bq, gq);   // Q: tf32, pre-scaled invt/8
    sgemm_tc<2><<<dim3(8, 64), 256>>>(his, Wk, bk, gk);   // K: tf32
    sgemm_tc<2><<<dim3(8, 64), 256>>>(his, Wv, bv, gv);   // V: tf32
    attn_tc<<<dim3(Hh, Ss/128, Bb), 256, ATT_SMEM>>>();
    sgemm_tc<1><<<dim3(8, 64), 256>>>(ga, Wo, bo, out);   // O: fp32 + mask-zero
}